// round 8
// baseline (speedup 1.0000x reference)
#include <cuda_runtime.h>

// B=4, H=256, W=256 torus. mu-subsystem only. Persistent kernel:
// 128 blocks (1/SM) x 512 threads; 16 warps x (9 rows x 32 cols) in regs.
// Region 144x32, interior 128x16, T=8, 13 periods (12x8 + 4).
// Period handoff via per-block neighbor flags (no global barrier).
#define BHW 262144
#define NBLOCKS 128

__device__ float  g_mu[2][BHW];
__device__ float  g_v [2][BHW];
__device__ float4 g_c [BHW];          // 0.01*(ex, ey, eu0, el1)
__device__ float2 g_ac[BHW];          // 0.01*(2*uw1, uw2*y)
__device__ volatile unsigned g_flag[NBLOCKS];

// ---------------- init ----------------
__global__ __launch_bounds__(256) void init_kernel(const float* __restrict__ y,
                                                   const float2* __restrict__ ew2,
                                                   const float2* __restrict__ un2) {
    const int p = blockIdx.x * 256 + threadIdx.x;
    const int base = p & ~65535;
    const int i    = p &  65535;
    const int row  = i & ~255;
    const int pu = base | ((i + 65280) & 65535);
    const int pl = base | row | ((i + 255) & 255);

    const float yv = y[p];
    const float2 e  = ew2[p];
    const float  eu = ew2[pu].x;
    const float  el = ew2[pl].y;
    const float2 u  = un2[p];

    g_mu[0][p] = yv;
    g_v [0][p] = 0.0f;
    g_c [p]    = make_float4(0.01f * e.x, 0.01f * e.y, 0.01f * eu, 0.01f * el);
    g_ac[p]    = make_float2(0.01f * 2.0f * u.x, 0.01f * u.y * yv);
    if (p < NBLOCKS) g_flag[p] = 0u;
}

// ---------------- persistent kernel ----------------
__global__ __launch_bounds__(512, 1) void persist_kernel(float* __restrict__ out) {
    __shared__ float s_top[2][16][32];
    __shared__ float s_bot[2][16][32];

    const int lane = threadIdx.x & 31;
    const int w    = threadIdx.x >> 5;           // band 0..15
    const int blk  = blockIdx.x;                 // 4 img x 2 vtile x 16 htile
    const int img  = blk >> 5;
    const int tv   = (blk >> 4) & 1;
    const int th   = blk & 15;
    const int base = img << 16;
    const int gcol = (th * 16 - 8 + lane) & 255;
    const int r0   = tv * 128 - 8 + w * 9;

    // 5 neighbor blocks supplying my halo: L, R, vertical-other, 2 diagonals.
    int nb = -1;
    {
        const int thL = (th + 15) & 15, thR = (th + 1) & 15, tvO = tv ^ 1;
        if      (threadIdx.x == 0) nb = (img << 5) | (tv  << 4) | thL;
        else if (threadIdx.x == 1) nb = (img << 5) | (tv  << 4) | thR;
        else if (threadIdx.x == 2) nb = (img << 5) | (tvO << 4) | th;
        else if (threadIdx.x == 3) nb = (img << 5) | (tvO << 4) | thL;
        else if (threadIdx.x == 4) nb = (img << 5) | (tvO << 4) | thR;
    }

    // cz[r] == cx[r-1]; only row 0 needs explicit cz0.
    float mu[9], v[9], cx[9], cy[9], cw[9], ax[9], ay[9], cz0;

    #pragma unroll
    for (int r = 0; r < 9; ++r) {
        const int p = base + (((r0 + r) & 255) << 8) + gcol;
        mu[r] = g_mu[0][p];
        v[r]  = g_v[0][p];
        const float4 c = g_c[p];
        cx[r] = c.x; cy[r] = c.y; cw[r] = c.w;
        if (r == 0) cz0 = c.z;
        const float2 a = g_ac[p];
        ax[r] = a.x; ay[r] = a.y;
    }

    for (int per = 0; per < 13; ++per) {
        const int TT = (per < 12) ? 8 : 4;

        s_top[0][w][lane] = mu[0];
        s_bot[0][w][lane] = mu[8];
        __syncthreads();

        for (int it = 0; it < TT; ++it) {
            const int rb = it & 1;
            float old_above = (w > 0)  ? s_bot[rb][w - 1][lane] : mu[0];
            const float dn  = (w < 15) ? s_top[rb][w + 1][lane] : mu[8];

            #pragma unroll
            for (int r = 0; r < 9; ++r) {
                const float cur   = mu[r];
                const float below = (r < 8) ? mu[r + 1] : dn;
                const float left  = __shfl_up_sync(0xFFFFFFFFu, cur, 1);
                const float right = __shfl_down_sync(0xFFFFFFFFu, cur, 1);
                const float czr   = (r == 0) ? cz0 : cx[r - 1];

                float dmu = fmaf(ax[r], cur, ay[r]);
                dmu = fmaf(cx[r], below, dmu);
                dmu = fmaf(cy[r], right, dmu);
                dmu = fmaf(czr,  old_above, dmu);
                dmu = fmaf(cw[r], left, dmu);

                v[r]  = fmaf(0.7f, v[r], dmu);
                mu[r] = fminf(fmaxf(cur + v[r], 0.0f), 63.0f);
                old_above = cur;
            }
            s_top[rb ^ 1][w][lane] = mu[0];
            s_bot[rb ^ 1][w][lane] = mu[8];
            __syncthreads();
        }

        const int d = (per + 1) & 1;

        // Write exact interior: region rows 8..135, cols 8..23.
        if (lane >= 8 && lane < 24) {
            #pragma unroll
            for (int r = 0; r < 9; ++r) {
                const int R = w * 9 + r;
                if (R >= 8 && R < 136) {
                    const int p = base + (((r0 + r) & 255) << 8) + gcol;
                    g_mu[d][p] = mu[r];
                    g_v [d][p] = v[r];
                    if (per == 12) out[p] = mu[r];
                }
            }
        }

        if (per == 12) break;

        // ---- release: my period-per interior is published ----
        __threadfence();
        __syncthreads();
        if (threadIdx.x == 0) g_flag[blk] = (unsigned)(per + 1);

        // ---- acquire: wait for the 5 halo-supplying neighbors ----
        if (nb >= 0) {
            while (g_flag[nb] <= (unsigned)per) { }
            __threadfence();      // CCTL.IVALL: invalidate L1 before halo reload
        }
        __syncthreads();

        // Reload halo cells' mu,v (interior stays in registers).
        #pragma unroll
        for (int r = 0; r < 9; ++r) {
            const int R = w * 9 + r;
            const bool interior = (R >= 8) && (R < 136) && (lane >= 8) && (lane < 24);
            if (!interior) {
                const int p = base + (((r0 + r) & 255) << 8) + gcol;
                mu[r] = g_mu[d][p];
                v[r]  = g_v[d][p];
            }
        }
    }
}

// ---------------- launch ----------------
extern "C" void kernel_launch(void* const* d_in, const int* in_sizes, int n_in,
                              void* d_out, int out_size) {
    const float* y  = (const float*)d_in[0];
    const float* ew = (const float*)d_in[1];
    const float* un = (const float*)d_in[2];
    float* out = (float*)d_out;

    init_kernel<<<1024, 256>>>(y, (const float2*)ew, (const float2*)un);
    persist_kernel<<<NBLOCKS, 512>>>(out);
}

// round 9
// speedup vs baseline: 1.9876x; 1.9876x over previous
#include <cuda_runtime.h>
#include <cstdint>

// B=4, H=256, W=256 torus. mu-subsystem only. Persistent kernel:
// 128 blocks (1/SM) x 512 threads; 16 warps x (9 rows x 32 cols) in regs.
// Region 144x32, interior 128x16, T=8, 13 periods (12x8 + 4).
// Per-iteration sync: split mbarrier (arrive after boundary write, wait
// after interior compute) instead of monolithic __syncthreads.
#define BHW 262144
#define NBLOCKS 128

__device__ float  g_mu[2][BHW];
__device__ float  g_v [2][BHW];
__device__ float4 g_c [BHW];          // 0.01*(ex, ey, eu0, el1)
__device__ float2 g_ac[BHW];          // 0.01*(2*uw1, uw2*y)
__device__ unsigned g_bar;            // global period barrier counter

// ---------------- init ----------------
__global__ __launch_bounds__(256) void init_kernel(const float* __restrict__ y,
                                                   const float2* __restrict__ ew2,
                                                   const float2* __restrict__ un2) {
    const int p = blockIdx.x * 256 + threadIdx.x;
    const int base = p & ~65535;
    const int i    = p &  65535;
    const int row  = i & ~255;
    const int pu = base | ((i + 65280) & 65535);
    const int pl = base | row | ((i + 255) & 255);

    const float yv = y[p];
    const float2 e  = ew2[p];
    const float  eu = ew2[pu].x;
    const float  el = ew2[pl].y;
    const float2 u  = un2[p];

    g_mu[0][p] = yv;
    g_v [0][p] = 0.0f;
    g_c [p]    = make_float4(0.01f * e.x, 0.01f * e.y, 0.01f * eu, 0.01f * el);
    g_ac[p]    = make_float2(0.01f * 2.0f * u.x, 0.01f * u.y * yv);
    if (p == 0) g_bar = 0u;
}

__device__ __forceinline__ uint32_t smem_u32(const void* p) {
    uint32_t a;
    asm("{ .reg .u64 t; cvta.to.shared.u64 t, %1; cvt.u32.u64 %0, t; }"
        : "=r"(a) : "l"(p));
    return a;
}

// ---------------- persistent kernel ----------------
__global__ __launch_bounds__(512, 1) void persist_kernel(float* __restrict__ out) {
    __shared__ float s_top[2][16][32];
    __shared__ float s_bot[2][16][32];
    __shared__ unsigned long long s_mbar;

    const int lane = threadIdx.x & 31;
    const int w    = threadIdx.x >> 5;           // band 0..15
    const int blk  = blockIdx.x;                 // 4 img x 2 vtile x 16 htile
    const int base = (blk >> 5) << 16;
    const int tv   = (blk >> 4) & 1;
    const int th   = blk & 15;
    const int gcol = (th * 16 - 8 + lane) & 255;
    const int r0   = tv * 128 - 8 + w * 9;

    const uint32_t mbar = smem_u32(&s_mbar);
    if (threadIdx.x == 0) {
        asm volatile("mbarrier.init.shared.b64 [%0], %1;" :: "r"(mbar), "r"(512) : "memory");
    }
    __syncthreads();

    // cz[r] == cx[r-1]; only row 0 needs explicit cz0.
    float mu[9], v[9], cx[9], cy[9], cw[9], ax[9], ay[9], cz0;

    #pragma unroll
    for (int r = 0; r < 9; ++r) {
        const int p = base + (((r0 + r) & 255) << 8) + gcol;
        mu[r] = g_mu[0][p];
        v[r]  = g_v[0][p];
        const float4 c = g_c[p];
        cx[r] = c.x; cy[r] = c.y; cw[r] = c.w;
        if (r == 0) cz0 = c.z;
        const float2 a = g_ac[p];
        ax[r] = a.x; ay[r] = a.y;
    }

    unsigned target = 0;
    int phase = 0;

    for (int per = 0; per < 13; ++per) {
        const int TT = (per < 12) ? 8 : 4;

        // publish period-start boundaries, arrive
        s_top[0][w][lane] = mu[0];
        s_bot[0][w][lane] = mu[8];
        asm volatile("mbarrier.arrive.shared.b64 _, [%0];" :: "r"(mbar) : "memory");

        for (int it = 0; it < TT; ++it) {
            const int rb = it & 1;
            const float old0 = mu[0], old1 = mu[1];
            const float old7 = mu[7], old8 = mu[8];

            // ---- interior rows 1..7: need only own old registers ----
            float old_above = old0;
            #pragma unroll
            for (int r = 1; r < 8; ++r) {
                const float cur   = mu[r];
                const float below = mu[r + 1];                 // still old
                const float left  = __shfl_up_sync(0xFFFFFFFFu, cur, 1);
                const float right = __shfl_down_sync(0xFFFFFFFFu, cur, 1);

                float dmu = fmaf(ax[r], cur, ay[r]);
                dmu = fmaf(cx[r], below, dmu);
                dmu = fmaf(cy[r], right, dmu);
                dmu = fmaf(cx[r - 1], old_above, dmu);
                dmu = fmaf(cw[r], left, dmu);

                v[r]  = fmaf(0.7f, v[r], dmu);
                old_above = cur;
                mu[r] = fminf(fmaxf(cur + v[r], 0.0f), 63.0f);
            }

            // ---- wait for neighbor boundary values of this phase ----
            {
                uint32_t done;
                asm volatile(
                    "{\n\t.reg .pred p;\n\t"
                    "mbarrier.try_wait.parity.acquire.cta.shared::cta.b64 p, [%1], %2;\n\t"
                    "selp.b32 %0, 1, 0, p;\n\t}"
                    : "=r"(done) : "r"(mbar), "r"(phase) : "memory");
                if (!done) {
                    asm volatile(
                        "{\n\t.reg .pred P1;\n\t"
                        "W_%=:\n\t"
                        "mbarrier.try_wait.parity.acquire.cta.shared::cta.b64 P1, [%0], %1, 0x989680;\n\t"
                        "@P1 bra.uni D_%=;\n\t"
                        "bra.uni W_%=;\n\t"
                        "D_%=:\n\t}"
                        :: "r"(mbar), "r"(phase) : "memory");
                }
                phase ^= 1;
            }

            const float nb_above = (w > 0)  ? s_bot[rb][w - 1][lane] : old0;
            const float nb_below = (w < 15) ? s_top[rb][w + 1][lane] : old8;

            // ---- row 0 ----
            {
                const float left  = __shfl_up_sync(0xFFFFFFFFu, old0, 1);
                const float right = __shfl_down_sync(0xFFFFFFFFu, old0, 1);
                float dmu = fmaf(ax[0], old0, ay[0]);
                dmu = fmaf(cx[0], old1, dmu);
                dmu = fmaf(cy[0], right, dmu);
                dmu = fmaf(cz0,  nb_above, dmu);
                dmu = fmaf(cw[0], left, dmu);
                v[0]  = fmaf(0.7f, v[0], dmu);
                mu[0] = fminf(fmaxf(old0 + v[0], 0.0f), 63.0f);
            }
            // ---- row 8 ----
            {
                const float left  = __shfl_up_sync(0xFFFFFFFFu, old8, 1);
                const float right = __shfl_down_sync(0xFFFFFFFFu, old8, 1);
                float dmu = fmaf(ax[8], old8, ay[8]);
                dmu = fmaf(cx[8], nb_below, dmu);
                dmu = fmaf(cy[8], right, dmu);
                dmu = fmaf(cx[7], old7, dmu);
                dmu = fmaf(cw[8], left, dmu);
                v[8]  = fmaf(0.7f, v[8], dmu);
                mu[8] = fminf(fmaxf(old8 + v[8], 0.0f), 63.0f);
            }

            // publish new boundaries for next iteration, arrive early
            if (it < TT - 1) {
                s_top[rb ^ 1][w][lane] = mu[0];
                s_bot[rb ^ 1][w][lane] = mu[8];
                asm volatile("mbarrier.arrive.shared.b64 _, [%0];" :: "r"(mbar) : "memory");
            }
        }

        const int d = (per + 1) & 1;

        // Write exact interior: region rows 8..135, cols 8..23.
        if (lane >= 8 && lane < 24) {
            #pragma unroll
            for (int r = 0; r < 9; ++r) {
                const int R = w * 9 + r;
                if (R >= 8 && R < 136) {
                    const int p = base + (((r0 + r) & 255) << 8) + gcol;
                    g_mu[d][p] = mu[r];
                    g_v [d][p] = v[r];
                    if (per == 12) out[p] = mu[r];
                }
            }
        }

        if (per == 12) break;

        // ---- global period barrier (single counter, proven) ----
        __threadfence();
        __syncthreads();
        target += NBLOCKS;
        if (threadIdx.x == 0) {
            atomicAdd(&g_bar, 1u);
            while (*((volatile unsigned*)&g_bar) < target) { }
            __threadfence();
        }
        __syncthreads();

        // Reload halo cells' mu,v (interior stays in registers).
        #pragma unroll
        for (int r = 0; r < 9; ++r) {
            const int R = w * 9 + r;
            const bool interior = (R >= 8) && (R < 136) && (lane >= 8) && (lane < 24);
            if (!interior) {
                const int p = base + (((r0 + r) & 255) << 8) + gcol;
                mu[r] = g_mu[d][p];
                v[r]  = g_v[d][p];
            }
        }
    }
}

// ---------------- launch ----------------
extern "C" void kernel_launch(void* const* d_in, const int* in_sizes, int n_in,
                              void* d_out, int out_size) {
    const float* y  = (const float*)d_in[0];
    const float* ew = (const float*)d_in[1];
    const float* un = (const float*)d_in[2];
    float* out = (float*)d_out;

    init_kernel<<<1024, 256>>>(y, (const float2*)ew, (const float2*)un);
    persist_kernel<<<NBLOCKS, 512>>>(out);
}